// round 14
// baseline (speedup 1.0000x reference)
#include <cuda_runtime.h>
#include <math.h>

#define BB 16
#define GG 2048
#define CC 128
#define KK 16
#define TMM 128        // rows per mlp block
#define QW 8           // queries (warps) per knn block
#define SCAP 376       // E[surv]=128, sigma~30: P(>376) ~ 4e-8/query
#define MLP_T 256

__device__ int g_knn[BB * GG * KK];

// ---------------------------------------------------------------------------
__device__ __forceinline__ unsigned okey(unsigned u) {
    unsigned m = ((unsigned)(((int)u) >> 31)) | 0x80000000u;
    return u ^ m;
}
__device__ __forceinline__ unsigned long long dup2(float x) {
    unsigned long long r; unsigned a = __float_as_uint(x);
    asm("mov.b64 %0, {%1, %1};" : "=l"(r) : "r"(a));
    return r;
}
__device__ __forceinline__ float2 unpack2(unsigned long long v) {
    unsigned lo, hi;
    asm("mov.b64 {%0, %1}, %2;" : "=r"(lo), "=r"(hi) : "l"(v));
    return make_float2(__uint_as_float(lo), __uint_as_float(hi));
}
#define FMA2(acc, a, b) \
    asm("fma.rn.f32x2 %0, %1, %2, %0;" : "+l"(acc) : "l"(a), "l"(b))

// ---------------------------------------------------------------------------
// KNN: R12 logic. ONE change: phase-A binary-search count uses a 4-ballot
// bit-sliced sum (independent ballots, overlapped latency) instead of a
// serialized __reduce_add_sync chain. Exact same count value.
// 56.4KB/block -> 4 blocks/SM.
// ---------------------------------------------------------------------------
__global__ __launch_bounds__(256, 4) void knn_kernel(const float* __restrict__ xyz) {
    extern __shared__ unsigned char ksm[];
    float4* pts = (float4*)ksm;                                       // 32KB
    unsigned long long* svAll = (unsigned long long*)(ksm + GG * 16); // 23.5KB

    const int tid = threadIdx.x;
    const int b = blockIdx.y;
    const float* p = xyz + (size_t)b * GG * 3;
    for (int i = tid; i < GG; i += 256) {
        float x = p[i * 3 + 0], y = p[i * 3 + 1], z = p[i * 3 + 2];
        pts[i] = make_float4(x, y, z, x * x + y * y + z * z);
    }
    __syncthreads();

    const int w = tid >> 5, lane = tid & 31;
    const unsigned FULL = 0xffffffffu;
    const unsigned lmask = (1u << lane) - 1u;
    unsigned long long* sv = svAll + (size_t)w * SCAP;

    const int q = blockIdx.x * QW + w;
    const float4 qp = pts[q];
    const float qx = qp.x, qy = qp.y, qz = qp.z;
    // d' = s - 2*dot (order-preserving shift of d2 per query)

    // ---- phase A: 256-point contiguous sample (conflict-free LDS),
    //      binary search exact sample-16th -> tau (valid upper bound) ----
    unsigned skey[8]; unsigned lmax = 0;
#pragma unroll
    for (int j = 0; j < 8; ++j) {
        int c = j * 32 + lane;
        float4 pc = pts[c];
        float t = fmaf(qx, pc.x, fmaf(qy, pc.y, qz * pc.z));
        float d = fmaf(-2.f, t, pc.w);
        skey[j] = okey(__float_as_uint(d));
        lmax = max(lmax, skey[j]);
    }
    unsigned lo = 0, hi = __reduce_max_sync(FULL, lmax);
#pragma unroll
    for (int step = 0; step < 18; ++step) {
        unsigned mid = lo + ((hi - lo) >> 1);
        unsigned c = 0;
#pragma unroll
        for (int j = 0; j < 8; ++j) c += (skey[j] <= mid) ? 1u : 0u;
        // bit-sliced warp sum of c in [0,8]: 4 independent ballots
        unsigned b0 = __ballot_sync(FULL, (c & 1u) != 0u);
        unsigned b1 = __ballot_sync(FULL, (c & 2u) != 0u);
        unsigned b2 = __ballot_sync(FULL, (c & 4u) != 0u);
        unsigned b3 = __ballot_sync(FULL, (c & 8u) != 0u);
        unsigned tot = __popc(b0) + (__popc(b1) << 1) +
                       (__popc(b2) << 2) + (__popc(b3) << 3);
        if (tot >= KK) hi = mid; else lo = mid + 1;
    }
    unsigned fbits = (hi & 0x80000000u) ? (hi ^ 0x80000000u) : ~hi;
    float tauf = __uint_as_float(fbits);
    if (!(tauf == tauf)) tauf = __uint_as_float(0x7f800000u);

    // ---- phase B: filter + compact (4-way ILP) ----
    unsigned scnt = 0;
    for (int j = 0; j < GG / 128; ++j) {
        const int c0 = j * 128 + lane;
        const float4 p0 = pts[c0], p1 = pts[c0 + 32], p2 = pts[c0 + 64], p3 = pts[c0 + 96];
        float t0 = fmaf(qx, p0.x, fmaf(qy, p0.y, qz * p0.z));
        float t1 = fmaf(qx, p1.x, fmaf(qy, p1.y, qz * p1.z));
        float t2 = fmaf(qx, p2.x, fmaf(qy, p2.y, qz * p2.z));
        float t3 = fmaf(qx, p3.x, fmaf(qy, p3.y, qz * p3.z));
        float d0 = fmaf(-2.f, t0, p0.w);
        float d1 = fmaf(-2.f, t1, p1.w);
        float d2 = fmaf(-2.f, t2, p2.w);
        float d3 = fmaf(-2.f, t3, p3.w);
        bool s0 = (d0 <= tauf), s1 = (d1 <= tauf), s2 = (d2 <= tauf), s3 = (d3 <= tauf);
        unsigned m0 = __ballot_sync(FULL, s0);
        unsigned m1 = __ballot_sync(FULL, s1);
        unsigned m2 = __ballot_sync(FULL, s2);
        unsigned m3 = __ballot_sync(FULL, s3);
        unsigned base0 = scnt;
        unsigned base1 = base0 + __popc(m0);
        unsigned base2 = base1 + __popc(m1);
        unsigned base3 = base2 + __popc(m2);
        scnt = base3 + __popc(m3);
        unsigned pos0 = base0 + __popc(m0 & lmask);
        unsigned pos1 = base1 + __popc(m1 & lmask);
        unsigned pos2 = base2 + __popc(m2 & lmask);
        unsigned pos3 = base3 + __popc(m3 & lmask);
        if (s0 && pos0 < SCAP)
            sv[pos0] = ((unsigned long long)__float_as_uint(d0) << 32) | (unsigned)c0;
        if (s1 && pos1 < SCAP)
            sv[pos1] = ((unsigned long long)__float_as_uint(d1) << 32) | (unsigned)(c0 + 32);
        if (s2 && pos2 < SCAP)
            sv[pos2] = ((unsigned long long)__float_as_uint(d2) << 32) | (unsigned)(c0 + 64);
        if (s3 && pos3 < SCAP)
            sv[pos3] = ((unsigned long long)__float_as_uint(d3) << 32) | (unsigned)(c0 + 96);
    }
    if (scnt > SCAP) scnt = SCAP;
    unsigned padded = (scnt + 31u) & ~31u;
    for (unsigned i = scnt + lane; i < padded; i += 32) sv[i] = ~0ULL;
    __syncwarp();

    // okey conversion on survivors only (padding stays max key)
    const int niter = padded >> 5;
    for (int i = 0; i < niter; ++i) {
        unsigned e = i * 32 + lane;
        if (e < scnt) {
            unsigned long long pk = sv[e];
            unsigned kb = okey((unsigned)(pk >> 32));
            sv[e] = ((unsigned long long)kb << 32) | (unsigned)pk;
        }
    }
    __syncwarp();

    // ---- phase C: exact 16-smallest via 5-bit ballot radix ----
    unsigned need = KK;
    unsigned long long prefix = 0;
    int s = 60;
    bool first = true;
    for (;;) {
        unsigned cntl = 0;
        for (int i = 0; i < niter; ++i) {
            unsigned long long pk = sv[i * 32 + lane];
            bool ok = first || ((pk >> (s + 5)) == prefix);
            unsigned d = (unsigned)(pk >> s) & 31u;
            unsigned mok = __ballot_sync(FULL, ok);
            unsigned m0 = __ballot_sync(FULL, ok && (d & 1u));
            unsigned m1 = __ballot_sync(FULL, ok && (d & 2u));
            unsigned m2 = __ballot_sync(FULL, ok && (d & 4u));
            unsigned m3 = __ballot_sync(FULL, ok && (d & 8u));
            unsigned m4 = __ballot_sync(FULL, ok && (d & 16u));
            unsigned sel = mok;
            sel &= (lane & 1)  ? m0 : ~m0;
            sel &= (lane & 2)  ? m1 : ~m1;
            sel &= (lane & 4)  ? m2 : ~m2;
            sel &= (lane & 8)  ? m3 : ~m3;
            sel &= (lane & 16) ? m4 : ~m4;
            cntl += __popc(sel);
        }
        unsigned run = cntl;
#pragma unroll
        for (int off = 1; off < 32; off <<= 1) {
            unsigned n = __shfl_up_sync(FULL, run, off);
            if (lane >= off) run += n;
        }
        unsigned excl = run - cntl;
        bool has = (excl < need) && (run >= need);
        unsigned hm = __ballot_sync(FULL, has);
        int src = __ffs(hm) - 1;
        unsigned base = __shfl_sync(FULL, excl, src);
        unsigned cnt  = __shfl_sync(FULL, cntl, src);
        prefix = (prefix << 5) | (unsigned)src;
        need -= base;
        first = false;
        if (need == cnt || s == 0) break;
        s -= 5;
    }

    unsigned outc = 0;
    int* outp = g_knn + ((size_t)b * GG + q) * KK;
    for (int i = 0; i < niter && outc < KK; ++i) {
        unsigned long long pk = sv[i * 32 + lane];
        bool sel = (pk >> s) <= prefix;
        unsigned m = __ballot_sync(FULL, sel);
        unsigned pos = outc + __popc(m & lmask);
        if (sel && pos < KK) outp[pos] = (int)(unsigned)pk;
        outc += __popc(m);
    }
}

// ---------------------------------------------------------------------------
// MLP: EXACT R7/R12 kernel (measured 89.0-90.1us four times; untouched).
// ---------------------------------------------------------------------------
#define MLP_SMEM (TMM * CC * 4 + 64 * CC * 4 + 2 * CC * 4 + TMM * KK * 4)

__device__ __forceinline__ void stage_w_half(const float* __restrict__ W, int crow0,
                                             float* __restrict__ Ws, int tid) {
    for (int idx = tid; idx < 64 * 32; idx += MLP_T) {
        int c = idx >> 5, jq = idx & 31;
        float4 v = *(const float4*)(W + (size_t)(crow0 + c) * CC + jq * 4);
        int tx = jq >> 1, k = jq & 1, bsw = (tx >> 2) & 1;
        int phys = 2 * tx + ((k + bsw) & 1);
        *(float4*)(Ws + c * CC + phys * 4) = v;
    }
}

__device__ __forceinline__ void gemm_half(const float* __restrict__ As,
                                          const float* __restrict__ Ws,
                                          int r0, int olo, int ohi, int cbase,
                                          unsigned long long (&acc)[8][4]) {
    const char* wb = (const char*)Ws;
#pragma unroll 2
    for (int c = 0; c < 64; ++c) {
        unsigned long long av[8];
#pragma unroll
        for (int i = 0; i < 8; ++i) av[i] = dup2(As[(r0 + i) * CC + cbase + c]);
        const char* base = wb + c * 512;
        const ulonglong2 wl = *(const ulonglong2*)(base + olo);
        const ulonglong2 wh = *(const ulonglong2*)(base + ohi);
        const unsigned long long wv[4] = {wl.x, wl.y, wh.x, wh.y};
#pragma unroll
        for (int i = 0; i < 8; ++i)
#pragma unroll
            for (int pp = 0; pp < 4; ++pp)
                FMA2(acc[i][pp], av[i], wv[pp]);
    }
}

__global__ __launch_bounds__(MLP_T, 2) void mlp_kernel(const float* __restrict__ feat,
                                                       const float* __restrict__ W1,
                                                       const float* __restrict__ b1,
                                                       const float* __restrict__ W2,
                                                       const float* __restrict__ b2,
                                                       float* __restrict__ out) {
    extern __shared__ __align__(16) float sm[];
    float* As   = sm;                   // TMM * CC row-major (64KB)
    float* Ws   = As + TMM * CC;        // 64 * CC (32KB, K-half of W)
    float* bs   = Ws + 64 * CC;         // 2 * CC
    int*   sidx = (int*)(bs + 2 * CC);  // TMM * KK

    const int tid = threadIdx.x;
    const int rowBase = blockIdx.x * TMM;
    const int b = rowBase >> 11;
    const float* fb = feat + (size_t)b * GG * CC;

    for (int i = tid; i < TMM * KK; i += MLP_T) sidx[i] = g_knn[(size_t)rowBase * KK + i];
    stage_w_half(W1, 0, Ws, tid);
    if (tid < CC) { bs[tid] = b1[tid]; bs[CC + tid] = b2[tid]; }
    __syncthreads();

    // gather + L2 pool -> As row-major
    {
        const int lane = tid & 31, warp = tid >> 5;
        for (int pass = 0; pass < TMM / 8; ++pass) {
            const int r = pass * 8 + warp;
            const int* ip = sidx + r * KK;
            float4 acc = make_float4(0.f, 0.f, 0.f, 0.f);
#pragma unroll
            for (int k = 0; k < KK; ++k) {
                const float4 f = *reinterpret_cast<const float4*>(
                    fb + (size_t)ip[k] * CC + lane * 4);
                acc.x = fmaf(f.x, f.x, acc.x);
                acc.y = fmaf(f.y, f.y, acc.y);
                acc.z = fmaf(f.z, f.z, acc.z);
                acc.w = fmaf(f.w, f.w, acc.w);
            }
            acc.x = sqrtf(acc.x); acc.y = sqrtf(acc.y);
            acc.z = sqrtf(acc.z); acc.w = sqrtf(acc.w);
            *reinterpret_cast<float4*>(As + r * CC + lane * 4) = acc;
        }
    }
    __syncthreads();

    const int ty = tid >> 4, tx = tid & 15;
    const int r0 = ty * 8, j0 = tx * 8;
    const int bsw = (tx >> 2) & 1;
    const int olo = (2 * tx + bsw) * 16;
    const int ohi = (2 * tx + 1 - bsw) * 16;

    // ---- GEMM1 (K-split) ----
    unsigned long long acc[8][4];
#pragma unroll
    for (int i = 0; i < 8; ++i)
#pragma unroll
        for (int pp = 0; pp < 4; ++pp) acc[i][pp] = 0ULL;

    gemm_half(As, Ws, r0, olo, ohi, 0, acc);
    __syncthreads();
    stage_w_half(W1, 64, Ws, tid);
    __syncthreads();
    gemm_half(As, Ws, r0, olo, ohi, 64, acc);

    // GELU epilogue
    float h[8][8];
#pragma unroll
    for (int i = 0; i < 8; ++i)
#pragma unroll
        for (int pp = 0; pp < 4; ++pp) {
            float2 v = unpack2(acc[i][pp]);
            float vx = v.x + bs[j0 + pp * 2 + 0];
            float vy = v.y + bs[j0 + pp * 2 + 1];
            h[i][pp * 2 + 0] = 0.5f * vx * (1.f + erff(vx * 0.70710678118654752f));
            h[i][pp * 2 + 1] = 0.5f * vy * (1.f + erff(vy * 0.70710678118654752f));
        }
    __syncthreads();

    // H -> As, W2 half0 -> Ws
#pragma unroll
    for (int i = 0; i < 8; ++i) {
        float* hp = As + (r0 + i) * CC + j0;
        *(float4*)(hp)     = make_float4(h[i][0], h[i][1], h[i][2], h[i][3]);
        *(float4*)(hp + 4) = make_float4(h[i][4], h[i][5], h[i][6], h[i][7]);
    }
    stage_w_half(W2, 0, Ws, tid);
    __syncthreads();

    // ---- GEMM2 (K-split) ----
    unsigned long long acc2[8][4];
#pragma unroll
    for (int i = 0; i < 8; ++i)
#pragma unroll
        for (int pp = 0; pp < 4; ++pp) acc2[i][pp] = 0ULL;

    gemm_half(As, Ws, r0, olo, ohi, 0, acc2);
    __syncthreads();
    stage_w_half(W2, 64, Ws, tid);
    __syncthreads();
    gemm_half(As, Ws, r0, olo, ohi, 64, acc2);

#pragma unroll
    for (int i = 0; i < 8; ++i) {
        float o[8];
#pragma unroll
        for (int pp = 0; pp < 4; ++pp) {
            float2 v = unpack2(acc2[i][pp]);
            o[pp * 2 + 0] = v.x + bs[CC + j0 + pp * 2 + 0];
            o[pp * 2 + 1] = v.y + bs[CC + j0 + pp * 2 + 1];
        }
        float* op = out + (size_t)(rowBase + r0 + i) * CC + j0;
        *(float4*)(op)     = make_float4(o[0], o[1], o[2], o[3]);
        *(float4*)(op + 4) = make_float4(o[4], o[5], o[6], o[7]);
    }
}

// ---------------------------------------------------------------------------
extern "C" void kernel_launch(void* const* d_in, const int* in_sizes, int n_in,
                              void* d_out, int out_size) {
    const float* xyz  = (const float*)d_in[0];
    const float* feat = (const float*)d_in[1];
    const float* W1   = (const float*)d_in[2];
    const float* b1   = (const float*)d_in[3];
    const float* W2   = (const float*)d_in[4];
    const float* b2   = (const float*)d_in[5];
    float* out = (float*)d_out;

    const int KNN_SMEM = GG * 16 + QW * SCAP * 8;   // 56.4 KB -> 4 blocks/SM
    cudaFuncSetAttribute(knn_kernel, cudaFuncAttributeMaxDynamicSharedMemorySize,
                         KNN_SMEM);
    dim3 gknn(GG / QW, BB);
    knn_kernel<<<gknn, 256, KNN_SMEM>>>(xyz);

    cudaFuncSetAttribute(mlp_kernel, cudaFuncAttributeMaxDynamicSharedMemorySize,
                         MLP_SMEM);
    mlp_kernel<<<(BB * GG) / TMM, MLP_T, MLP_SMEM>>>(feat, W1, b1, W2, b2, out);
}

// round 17
// speedup vs baseline: 1.0971x; 1.0971x over previous
#include <cuda_runtime.h>
#include <cstdint>
#include <math.h>

#define BB 16
#define GG 2048
#define CC 128
#define KK 16
#define TMM 128        // rows per mlp block
#define QW 8           // queries (warps) per knn block
#define SCAP 368       // E[surv]~133, sigma~30: ~mu+7.8sigma
#define MLP_T 256

__device__ float g_pool[BB * GG * CC];   // pooled L2 norms (16.7 MB scratch)

// ---------------------------------------------------------------------------
__device__ __forceinline__ unsigned okey(unsigned u) {
    unsigned m = ((unsigned)(((int)u) >> 31)) | 0x80000000u;
    return u ^ m;
}
__device__ __forceinline__ unsigned long long dup2(float x) {
    unsigned long long r; unsigned a = __float_as_uint(x);
    asm("mov.b64 %0, {%1, %1};" : "=l"(r) : "r"(a));
    return r;
}
__device__ __forceinline__ float2 unpack2(unsigned long long v) {
    unsigned lo, hi;
    asm("mov.b64 {%0, %1}, %2;" : "=r"(lo), "=r"(hi) : "l"(v));
    return make_float2(__uint_as_float(lo), __uint_as_float(hi));
}
#define FMA2(acc, a, b) \
    asm("fma.rn.f32x2 %0, %1, %2, %0;" : "+l"(acc) : "l"(a), "l"(b))

// ---------------------------------------------------------------------------
// KNN + fused gather/pool. Select logic = R12 champion; emit goes to a per-warp
// smem index buffer; then this warp gathers its query's 16 feat rows and
// writes the pooled L2-norm row to g_pool (overlaps knn's idle memory pipes).
// smem: pts 32KB + sv 23KB + idx 0.5KB = 55.5KB -> 4 blocks/SM.
// ---------------------------------------------------------------------------
__global__ __launch_bounds__(256, 4) void knn_kernel(const float* __restrict__ xyz,
                                                     const float* __restrict__ feat) {
    extern __shared__ unsigned char ksm[];
    float4* pts = (float4*)ksm;                                        // 32KB
    unsigned long long* svAll = (unsigned long long*)(ksm + GG * 16);  // 23KB
    int* idxAll = (int*)(ksm + GG * 16 + QW * SCAP * 8);               // 512B

    const int tid = threadIdx.x;
    const int b = blockIdx.y;
    const float* p = xyz + (size_t)b * GG * 3;
    for (int i = tid; i < GG; i += 256) {
        float x = p[i * 3 + 0], y = p[i * 3 + 1], z = p[i * 3 + 2];
        pts[i] = make_float4(x, y, z, x * x + y * y + z * z);
    }
    __syncthreads();

    const int w = tid >> 5, lane = tid & 31;
    const unsigned FULL = 0xffffffffu;
    const unsigned lmask = (1u << lane) - 1u;
    unsigned long long* sv = svAll + (size_t)w * SCAP;
    int* idxb = idxAll + w * KK;

    const int q = blockIdx.x * QW + w;
    const float4 qp = pts[q];
    const float qx = qp.x, qy = qp.y, qz = qp.z;
    // d' = s - 2*dot (order-preserving shift of d2 per query)

    // ---- phase A: 256-point contiguous sample, binary search 16th -> tau ----
    unsigned skey[8]; unsigned lmax = 0;
#pragma unroll
    for (int j = 0; j < 8; ++j) {
        int c = j * 32 + lane;
        float4 pc = pts[c];
        float t = fmaf(qx, pc.x, fmaf(qy, pc.y, qz * pc.z));
        float d = fmaf(-2.f, t, pc.w);
        skey[j] = okey(__float_as_uint(d));
        lmax = max(lmax, skey[j]);
    }
    unsigned lo = 0, hi = __reduce_max_sync(FULL, lmax);
#pragma unroll
    for (int step = 0; step < 18; ++step) {
        unsigned mid = lo + ((hi - lo) >> 1);
        unsigned c = 0;
#pragma unroll
        for (int j = 0; j < 8; ++j) c += (skey[j] <= mid) ? 1u : 0u;
        c = __reduce_add_sync(FULL, c);
        if (c >= KK) hi = mid; else lo = mid + 1;
    }
    unsigned fbits = (hi & 0x80000000u) ? (hi ^ 0x80000000u) : ~hi;
    float tauf = __uint_as_float(fbits);
    if (!(tauf == tauf)) tauf = __uint_as_float(0x7f800000u);

    // ---- phase B: filter + compact (4-way ILP) ----
    unsigned scnt = 0;
    for (int j = 0; j < GG / 128; ++j) {
        const int c0 = j * 128 + lane;
        const float4 p0 = pts[c0], p1 = pts[c0 + 32], p2 = pts[c0 + 64], p3 = pts[c0 + 96];
        float t0 = fmaf(qx, p0.x, fmaf(qy, p0.y, qz * p0.z));
        float t1 = fmaf(qx, p1.x, fmaf(qy, p1.y, qz * p1.z));
        float t2 = fmaf(qx, p2.x, fmaf(qy, p2.y, qz * p2.z));
        float t3 = fmaf(qx, p3.x, fmaf(qy, p3.y, qz * p3.z));
        float d0 = fmaf(-2.f, t0, p0.w);
        float d1 = fmaf(-2.f, t1, p1.w);
        float d2 = fmaf(-2.f, t2, p2.w);
        float d3 = fmaf(-2.f, t3, p3.w);
        bool s0 = (d0 <= tauf), s1 = (d1 <= tauf), s2 = (d2 <= tauf), s3 = (d3 <= tauf);
        unsigned m0 = __ballot_sync(FULL, s0);
        unsigned m1 = __ballot_sync(FULL, s1);
        unsigned m2 = __ballot_sync(FULL, s2);
        unsigned m3 = __ballot_sync(FULL, s3);
        unsigned base0 = scnt;
        unsigned base1 = base0 + __popc(m0);
        unsigned base2 = base1 + __popc(m1);
        unsigned base3 = base2 + __popc(m2);
        scnt = base3 + __popc(m3);
        unsigned pos0 = base0 + __popc(m0 & lmask);
        unsigned pos1 = base1 + __popc(m1 & lmask);
        unsigned pos2 = base2 + __popc(m2 & lmask);
        unsigned pos3 = base3 + __popc(m3 & lmask);
        if (s0 && pos0 < SCAP)
            sv[pos0] = ((unsigned long long)__float_as_uint(d0) << 32) | (unsigned)c0;
        if (s1 && pos1 < SCAP)
            sv[pos1] = ((unsigned long long)__float_as_uint(d1) << 32) | (unsigned)(c0 + 32);
        if (s2 && pos2 < SCAP)
            sv[pos2] = ((unsigned long long)__float_as_uint(d2) << 32) | (unsigned)(c0 + 64);
        if (s3 && pos3 < SCAP)
            sv[pos3] = ((unsigned long long)__float_as_uint(d3) << 32) | (unsigned)(c0 + 96);
    }
    if (scnt > SCAP) scnt = SCAP;
    unsigned padded = (scnt + 31u) & ~31u;
    for (unsigned i = scnt + lane; i < padded; i += 32) sv[i] = ~0ULL;
    __syncwarp();

    // okey conversion on survivors only (padding stays max key)
    const int niter = padded >> 5;
    for (int i = 0; i < niter; ++i) {
        unsigned e = i * 32 + lane;
        if (e < scnt) {
            unsigned long long pk = sv[e];
            unsigned kb = okey((unsigned)(pk >> 32));
            sv[e] = ((unsigned long long)kb << 32) | (unsigned)pk;
        }
    }
    __syncwarp();

    // ---- phase C: exact 16-smallest via 5-bit ballot radix ----
    unsigned need = KK;
    unsigned long long prefix = 0;
    int s = 60;
    bool first = true;
    for (;;) {
        unsigned cntl = 0;
        for (int i = 0; i < niter; ++i) {
            unsigned long long pk = sv[i * 32 + lane];
            bool ok = first || ((pk >> (s + 5)) == prefix);
            unsigned d = (unsigned)(pk >> s) & 31u;
            unsigned mok = __ballot_sync(FULL, ok);
            unsigned m0 = __ballot_sync(FULL, ok && (d & 1u));
            unsigned m1 = __ballot_sync(FULL, ok && (d & 2u));
            unsigned m2 = __ballot_sync(FULL, ok && (d & 4u));
            unsigned m3 = __ballot_sync(FULL, ok && (d & 8u));
            unsigned m4 = __ballot_sync(FULL, ok && (d & 16u));
            unsigned sel = mok;
            sel &= (lane & 1)  ? m0 : ~m0;
            sel &= (lane & 2)  ? m1 : ~m1;
            sel &= (lane & 4)  ? m2 : ~m2;
            sel &= (lane & 8)  ? m3 : ~m3;
            sel &= (lane & 16) ? m4 : ~m4;
            cntl += __popc(sel);
        }
        unsigned run = cntl;
#pragma unroll
        for (int off = 1; off < 32; off <<= 1) {
            unsigned n = __shfl_up_sync(FULL, run, off);
            if (lane >= off) run += n;
        }
        unsigned excl = run - cntl;
        bool has = (excl < need) && (run >= need);
        unsigned hm = __ballot_sync(FULL, has);
        int src = __ffs(hm) - 1;
        unsigned base = __shfl_sync(FULL, excl, src);
        unsigned cnt  = __shfl_sync(FULL, cntl, src);
        prefix = (prefix << 5) | (unsigned)src;
        need -= base;
        first = false;
        if (need == cnt || s == 0) break;
        s -= 5;
    }

    // ---- emit: 16 indices into per-warp smem buffer ----
    unsigned outc = 0;
    for (int i = 0; i < niter && outc < KK; ++i) {
        unsigned e = i * 32 + lane;
        unsigned long long pk = sv[e];
        bool sel = (pk >> s) <= prefix;
        unsigned m = __ballot_sync(FULL, sel);
        unsigned pos = outc + __popc(m & lmask);
        if (sel && pos < KK) idxb[pos] = (int)(unsigned)pk;
        outc += __popc(m);
    }
    __syncwarp();

    // ---- fused gather + L2 pool: this warp pools its query's row ----
    {
        const float* fb = feat + (size_t)b * GG * CC;
        float4 acc = make_float4(0.f, 0.f, 0.f, 0.f);
#pragma unroll
        for (int k = 0; k < KK; ++k) {
            const int ix = idxb[k];   // warp-uniform smem broadcast
            const float4 f = *reinterpret_cast<const float4*>(
                fb + (size_t)ix * CC + lane * 4);
            acc.x = fmaf(f.x, f.x, acc.x);
            acc.y = fmaf(f.y, f.y, acc.y);
            acc.z = fmaf(f.z, f.z, acc.z);
            acc.w = fmaf(f.w, f.w, acc.w);
        }
        acc.x = sqrtf(acc.x); acc.y = sqrtf(acc.y);
        acc.z = sqrtf(acc.z); acc.w = sqrtf(acc.w);
        *reinterpret_cast<float4*>(
            g_pool + ((size_t)b * GG + q) * CC + lane * 4) = acc;
    }
}

// ---------------------------------------------------------------------------
// MLP: R7/R12 champion GEMM structure; pool phase replaced by a coalesced
// linear load of the pre-pooled A tile from g_pool.
// ---------------------------------------------------------------------------
#define MLP_SMEM (TMM * CC * 4 + 64 * CC * 4 + 2 * CC * 4)

__device__ __forceinline__ void stage_w_half(const float* __restrict__ W, int crow0,
                                             float* __restrict__ Ws, int tid) {
    for (int idx = tid; idx < 64 * 32; idx += MLP_T) {
        int c = idx >> 5, jq = idx & 31;
        float4 v = *(const float4*)(W + (size_t)(crow0 + c) * CC + jq * 4);
        int tx = jq >> 1, k = jq & 1, bsw = (tx >> 2) & 1;
        int phys = 2 * tx + ((k + bsw) & 1);
        *(float4*)(Ws + c * CC + phys * 4) = v;
    }
}

__device__ __forceinline__ void gemm_half(const float* __restrict__ As,
                                          const float* __restrict__ Ws,
                                          int r0, int olo, int ohi, int cbase,
                                          unsigned long long (&acc)[8][4]) {
    const char* wb = (const char*)Ws;
#pragma unroll 2
    for (int c = 0; c < 64; ++c) {
        unsigned long long av[8];
#pragma unroll
        for (int i = 0; i < 8; ++i) av[i] = dup2(As[(r0 + i) * CC + cbase + c]);
        const char* base = wb + c * 512;
        const ulonglong2 wl = *(const ulonglong2*)(base + olo);
        const ulonglong2 wh = *(const ulonglong2*)(base + ohi);
        const unsigned long long wv[4] = {wl.x, wl.y, wh.x, wh.y};
#pragma unroll
        for (int i = 0; i < 8; ++i)
#pragma unroll
            for (int pp = 0; pp < 4; ++pp)
                FMA2(acc[i][pp], av[i], wv[pp]);
    }
}

__global__ __launch_bounds__(MLP_T, 2) void mlp_kernel(const float* __restrict__ W1,
                                                       const float* __restrict__ b1,
                                                       const float* __restrict__ W2,
                                                       const float* __restrict__ b2,
                                                       float* __restrict__ out) {
    extern __shared__ __align__(16) float sm[];
    float* As = sm;                   // TMM * CC row-major (64KB)
    float* Ws = As + TMM * CC;        // 64 * CC (32KB, K-half of W)
    float* bs = Ws + 64 * CC;         // 2 * CC

    const int tid = threadIdx.x;
    const int rowBase = blockIdx.x * TMM;

    // load pre-pooled A tile (coalesced), stage W1 half0, biases
    {
        const float4* src = (const float4*)(g_pool + (size_t)rowBase * CC);
        for (int i = tid; i < TMM * CC / 4; i += MLP_T)
            ((float4*)As)[i] = src[i];
    }
    stage_w_half(W1, 0, Ws, tid);
    if (tid < CC) { bs[tid] = b1[tid]; bs[CC + tid] = b2[tid]; }
    __syncthreads();

    const int ty = tid >> 4, tx = tid & 15;
    const int r0 = ty * 8, j0 = tx * 8;
    const int bsw = (tx >> 2) & 1;
    const int olo = (2 * tx + bsw) * 16;
    const int ohi = (2 * tx + 1 - bsw) * 16;

    // ---- GEMM1 (K-split) ----
    unsigned long long acc[8][4];
#pragma unroll
    for (int i = 0; i < 8; ++i)
#pragma unroll
        for (int pp = 0; pp < 4; ++pp) acc[i][pp] = 0ULL;

    gemm_half(As, Ws, r0, olo, ohi, 0, acc);
    __syncthreads();
    stage_w_half(W1, 64, Ws, tid);
    __syncthreads();
    gemm_half(As, Ws, r0, olo, ohi, 64, acc);

    // GELU epilogue
    float h[8][8];
#pragma unroll
    for (int i = 0; i < 8; ++i)
#pragma unroll
        for (int pp = 0; pp < 4; ++pp) {
            float2 v = unpack2(acc[i][pp]);
            float vx = v.x + bs[j0 + pp * 2 + 0];
            float vy = v.y + bs[j0 + pp * 2 + 1];
            h[i][pp * 2 + 0] = 0.5f * vx * (1.f + erff(vx * 0.70710678118654752f));
            h[i][pp * 2 + 1] = 0.5f * vy * (1.f + erff(vy * 0.70710678118654752f));
        }
    __syncthreads();

    // H -> As, W2 half0 -> Ws
#pragma unroll
    for (int i = 0; i < 8; ++i) {
        float* hp = As + (r0 + i) * CC + j0;
        *(float4*)(hp)     = make_float4(h[i][0], h[i][1], h[i][2], h[i][3]);
        *(float4*)(hp + 4) = make_float4(h[i][4], h[i][5], h[i][6], h[i][7]);
    }
    stage_w_half(W2, 0, Ws, tid);
    __syncthreads();

    // ---- GEMM2 (K-split) ----
    unsigned long long acc2[8][4];
#pragma unroll
    for (int i = 0; i < 8; ++i)
#pragma unroll
        for (int pp = 0; pp < 4; ++pp) acc2[i][pp] = 0ULL;

    gemm_half(As, Ws, r0, olo, ohi, 0, acc2);
    __syncthreads();
    stage_w_half(W2, 64, Ws, tid);
    __syncthreads();
    gemm_half(As, Ws, r0, olo, ohi, 64, acc2);

#pragma unroll
    for (int i = 0; i < 8; ++i) {
        float o[8];
#pragma unroll
        for (int pp = 0; pp < 4; ++pp) {
            float2 v = unpack2(acc2[i][pp]);
            o[pp * 2 + 0] = v.x + bs[CC + j0 + pp * 2 + 0];
            o[pp * 2 + 1] = v.y + bs[CC + j0 + pp * 2 + 1];
        }
        float* op = out + (size_t)(rowBase + r0 + i) * CC + j0;
        *(float4*)(op)     = make_float4(o[0], o[1], o[2], o[3]);
        *(float4*)(op + 4) = make_float4(o[4], o[5], o[6], o[7]);
    }
}

// ---------------------------------------------------------------------------
extern "C" void kernel_launch(void* const* d_in, const int* in_sizes, int n_in,
                              void* d_out, int out_size) {
    const float* xyz  = (const float*)d_in[0];
    const float* feat = (const float*)d_in[1];
    const float* W1   = (const float*)d_in[2];
    const float* b1   = (const float*)d_in[3];
    const float* W2   = (const float*)d_in[4];
    const float* b2   = (const float*)d_in[5];
    float* out = (float*)d_out;

    const int KNN_SMEM = GG * 16 + QW * SCAP * 8 + QW * KK * 4; // 55.9 KB -> 4/SM
    cudaFuncSetAttribute(knn_kernel, cudaFuncAttributeMaxDynamicSharedMemorySize,
                         KNN_SMEM);
    dim3 gknn(GG / QW, BB);
    knn_kernel<<<gknn, 256, KNN_SMEM>>>(xyz, feat);

    cudaFuncSetAttribute(mlp_kernel, cudaFuncAttributeMaxDynamicSharedMemorySize,
                         MLP_SMEM);
    mlp_kernel<<<(BB * GG) / TMM, MLP_T, MLP_SMEM>>>(W1, b1, W2, b2, out);
}